// round 16
// baseline (speedup 1.0000x reference)
#include <cuda_runtime.h>

#define N_POS 8192
#define N_NEG 4000
#define N_TOT (N_POS + N_POS * N_NEG)   // 32,776,192 = 8192*4001
#define NT4   (N_TOT / 4)               // 8,194,048 vec4 tiles

constexpr int TPB2 = 512;               // pass-2 block size (16 warps)
constexpr int NB2  = 296;               // pass-2 blocks (2/SM, 64KB smem each)

// Static scratch (allocations forbidden).
__device__ float        g_pos[N_POS];
__device__ unsigned int g_rank[N_POS];  // merged counts (L2-resident, 32KB)
__device__ unsigned int g_ticket;

// ---------------- Pass 1: scan index (131MB), scatter the 8192 pos values ----
// Coalesced: the q-th int4 load of a warp has consecutive lanes. idx reads use
// the default cache policy ON PURPOSE: pass 2 re-reads idx (reversed) and we
// want the tail of idx resident in L2.
constexpr int TPB1  = 256;
constexpr int EPT1  = 32;                      // ints per thread (8 int4 loads)
constexpr int NBLK1 = N_TOT / (TPB1 * EPT1);   // 4001, exact

__global__ __launch_bounds__(TPB1) void k_scatter_pos(
    const int*   __restrict__ idx,
    const float* __restrict__ pv)
{
    const int4* idx4 = reinterpret_cast<const int4*>(idx);
    unsigned int base4 = blockIdx.x * (TPB1 * (EPT1 / 4));  // block's int4 base
    int4 r[8];
#pragma unroll
    for (int q = 0; q < 8; q++)
        r[q] = idx4[base4 + q * TPB1 + threadIdx.x];
#pragma unroll
    for (int q = 0; q < 8; q++) {
        unsigned int e0 = (base4 + q * TPB1 + threadIdx.x) * 4;
        int js[4] = {r[q].x, r[q].y, r[q].z, r[q].w};
#pragma unroll
        for (int k = 0; k < 4; k++) {
            unsigned int j = (unsigned int)js[k];
            if (j < N_POS) g_pos[j] = pv[e0 + k];   // rare: 8192/32.7M
        }
    }
    // Zero the merged-count array (32KB) + ticket; launch boundary orders it.
    if (blockIdx.x == 0) {
        for (int i = threadIdx.x; i < N_POS; i += TPB1) g_rank[i] = 0u;
        if (threadIdx.x == 0) g_ticket = 0u;
    }
}

// ---------------- Pass 2: count + fused finalize -----------------------------
// Rarer-side counting: pos>0 -> count (v >  pos), rank = 1+cnt
//                      pos<=0-> count (v <= pos), rank = 4001-cnt
// REVERSED traversal: pass 1 streamed idx low->high, so L2 holds the tail of
// idx; reading high->low turns a large fraction of idx reads into L2 hits.
// Epilogue: sparse REDG merge into the 32KB L2-resident g_rank; the LAST block
// (ticket) computes sample_mrr + mean and writes the output directly.
__global__ __launch_bounds__(TPB2) void k_count(
    const int*   __restrict__ idx,
    const float* __restrict__ pv,
    float*       __restrict__ out)
{
    __shared__ float        spos[N_POS];   // 32KB
    __shared__ unsigned int hist[N_POS];   // 32KB

    for (int i = threadIdx.x; i < N_POS; i += TPB2) {
        spos[i] = g_pos[i];                // coalesced table load
        hist[i] = 0u;
    }
    __syncthreads();

    const int4*   idx4 = reinterpret_cast<const int4*>(idx);
    const float4* pv4  = reinterpret_cast<const float4*>(pv);

    for (unsigned int u = blockIdx.x * TPB2 + threadIdx.x; u < NT4; u += NB2 * TPB2) {
        const unsigned int t = (NT4 - 1u) - u;           // reversed, coalesced
        int4   a = __ldcs(&idx4[t]);                     // last use of idx
        float4 v = __ldcs(&pv4[t]);                      // single use of pv
        int   js[4] = {a.x, a.y, a.z, a.w};
        float vs[4] = {v.x, v.y, v.z, v.w};
#pragma unroll
        for (int k = 0; k < 4; k++) {
            unsigned int j = (unsigned int)js[k];
            if (j >= N_POS) {
                unsigned int p = (j - N_POS) / N_NEG;   // const-div -> umulhi
                float pos = spos[p];                     // LDS (predicated)
                if ((vs[k] > pos) == (pos > 0.0f)) {     // rarer side (~25%)
                    atomicAdd(&hist[p], 1u);             // ATOMS, spread-addr
                }
            }
        }
    }
    __syncthreads();

    // Sparse flush straight into the merged array (skip zero rows).
    for (int i = threadIdx.x; i < N_POS; i += TPB2) {
        unsigned int c = hist[i];
        if (c) atomicAdd(&g_rank[i], c);   // REDG, coalesced, low contention
    }
    __threadfence();
    __syncthreads();

    // Last-finishing block performs the finalize (g_rank fully merged and
    // visible: every prior block's flush precedes its ticket increment).
    __shared__ bool last;
    if (threadIdx.x == 0)
        last = (atomicAdd(&g_ticket, 1u) == NB2 - 1);
    __syncthreads();
    if (!last) return;

    __shared__ float ssum[TPB2];
    float s = 0.0f;
    for (int p = threadIdx.x; p < N_POS; p += TPB2) {
        unsigned int cnt = g_rank[p];      // L2-hot 32KB
        float pos = g_pos[p];
        unsigned int rank = (pos > 0.0f) ? (1u + cnt)
                                         : (unsigned int)(N_NEG + 1) - cnt;
        float smrr = 1.0f / (float)rank;
        out[1 + p] = smrr;
        s += smrr;
    }
    ssum[threadIdx.x] = s;
    __syncthreads();
    for (int off = TPB2 / 2; off > 0; off >>= 1) {
        if (threadIdx.x < off) ssum[threadIdx.x] += ssum[threadIdx.x + off];
        __syncthreads();
    }
    if (threadIdx.x == 0) out[0] = ssum[0] / (float)N_POS;
}

extern "C" void kernel_launch(void* const* d_in, const int* in_sizes, int n_in,
                              void* d_out, int out_size)
{
    const float* pv  = (const float*)d_in[0];
    const int*   idx = (const int*)d_in[1];
    float* out = (float*)d_out;
    (void)in_sizes; (void)n_in; (void)out_size;

    k_scatter_pos<<<NBLK1, TPB1>>>(idx, pv);
    k_count<<<NB2, TPB2>>>(idx, pv, out);
}